// round 8
// baseline (speedup 1.0000x reference)
#include <cuda_runtime.h>
#include <math.h>

// DBI_44985487458968 — Davies-Bouldin index. N=2M x 64 f32, K=100.
// v2: MIO-dispatch-optimized accumulate:
//   - LDG.128 loads, 2 points per warp instruction (512B contiguous)
//   - permuted shared layout -> 2-way-max bank conflicts on sum atomics
//   - per-lane square partials into s2[K][16] (no shuffle reduction)
//   - chunked coalesced id loads + single per-lane-src shfl broadcast
// Finalize computes centroids, Si via  Sum||x-A||^2 = Sxx - 2A.Sx + n||A||^2,
// pairwise distances, row maxes, DBI scalar.

#define KC    100
#define DF    64
#define NSUM  (KC * DF)            // 6400 permuted sums
#define NS2   (KC * 16)            // 1600 square partials
#define NACC  (NSUM + NS2 + KC)    // + counts = 8100

__device__ float g_acc[NACC];
__device__ int   g_id64;           // 1 if clustering int64, 0 if int32

// ------------------------------------------------------- init + probe ----
__global__ void dbi_init_kernel(const unsigned int* __restrict__ cl_u32, int nprobe) {
    int i = blockIdx.x * blockDim.x + threadIdx.x;
    if (i < NACC) g_acc[i] = 0.0f;
    if (i == 0) {
        // int64 ids < 100 => every odd u32 word is zero.
        int any_nonzero = 0;
        for (int k = 0; k < nprobe; k++)
            any_nonzero |= (cl_u32[2 * k + 1] != 0u);
        g_id64 = !any_nonzero;
    }
}

// ---------------------------------------------------------- accumulate ----
__global__ __launch_bounds__(256) void dbi_accum_kernel(
    const float* __restrict__ pts,
    const void*  __restrict__ cl_raw,
    int n)
{
    __shared__ float s[NACC];      // [0,6400) sums(perm), [6400,8000) s2, [8000,8100) cnt
    for (int i = threadIdx.x; i < NACC; i += blockDim.x) s[i] = 0.0f;
    __syncthreads();

    const int id64 = g_id64;
    const unsigned int* clu = (const unsigned int*)cl_raw;  // view as u32 words
    const float4* f4 = (const float4*)pts;

    const int lane   = threadIdx.x & 31;
    const int half   = lane >> 4;        // 0 or 1
    const int l15    = lane & 15;
    const int wGlob  = (blockIdx.x * blockDim.x + threadIdx.x) >> 5;
    const int nWarps = (gridDim.x * blockDim.x) >> 5;

    float* s2   = s + NSUM;
    float* scnt = s + NSUM + NS2;

    const int nChunks = n >> 5;          // 32 points per chunk
    for (int ch = wGlob; ch < nChunks; ch += nWarps) {
        const int base = ch << 5;
        // coalesced id load: lane l -> id of point base+l (low u32 word)
        const int c_reg = (int)clu[id64 ? (unsigned)(2 * (base + lane))
                                        : (unsigned)(base + lane)];
        const size_t fbase = (size_t)base << 4;   // *16 float4 per point

        #pragma unroll 4
        for (int j = 0; j < 32; j += 2) {
            // one LDG.128: lanes 0-15 -> point base+j, lanes 16-31 -> base+j+1
            float4 v = __ldcs(&f4[fbase + (size_t)(j << 4) + lane]);
            // broadcast this half-warp's cluster id (single shfl, per-lane src)
            int c = __shfl_sync(0xffffffffu, c_reg, j + half);
            float sq = v.x * v.x + v.y * v.y + v.z * v.z + v.w * v.w;
            if ((unsigned)c < KC) {
                // permuted layout: dim d=4*l15+r stored at l15 + 16*r
                float* row = s + c * DF + l15;
                atomicAdd(row +  0, v.x);
                atomicAdd(row + 16, v.y);
                atomicAdd(row + 32, v.z);
                atomicAdd(row + 48, v.w);
                atomicAdd(&s2[c * 16 + l15], sq);
                if (l15 == 0) atomicAdd(&scnt[c], 1.0f);
            }
        }
    }

    // tail: points [nChunks*32, n), one warp per point, conflict-free lanes
    const int tail0 = nChunks << 5;
    const int ntail = n - tail0;
    if (wGlob < ntail) {
        const int p = tail0 + wGlob;
        const int c = (int)clu[id64 ? (unsigned)(2 * p) : (unsigned)p];
        float a0 = pts[(size_t)p * DF + lane];
        float a1 = pts[(size_t)p * DF + lane + 32];
        if ((unsigned)c < KC) {
            // write into permuted layout: dim d -> (d>>2) + 16*(d&3)
            int d0 = lane,      q0 = d0 >> 2, r0 = d0 & 3;
            int d1 = lane + 32, q1 = d1 >> 2, r1 = d1 & 3;
            atomicAdd(&s[c * DF + q0 + 16 * r0], a0);
            atomicAdd(&s[c * DF + q1 + 16 * r1], a1);
            atomicAdd(&s2[c * 16 + (lane & 15)], a0 * a0 + a1 * a1);
            if (lane == 0) atomicAdd(&scnt[c], 1.0f);
        }
    }

    __syncthreads();
    for (int i = threadIdx.x; i < NACC; i += blockDim.x) {
        float v = s[i];
        if (v != 0.0f) atomicAdd(&g_acc[i], v);
    }
}

// ------------------------------------------------------------ finalize ----
__global__ __launch_bounds__(128) void dbi_final_kernel(float* __restrict__ out) {
    __shared__ float A[KC][DF];
    __shared__ float Si[KC];
    __shared__ float rowmax[KC];
    const int tid = threadIdx.x;

    // centroids from permuted sums: Sx[c][d] = g_acc[c*64 + (d>>2) + 16*(d&3)]
    for (int i = tid; i < NSUM; i += blockDim.x) {
        int c = i / DF, d = i - c * DF;
        float cnt = 1.0f + g_acc[NSUM + NS2 + c];
        float sx  = g_acc[c * DF + (d >> 2) + 16 * (d & 3)];
        A[c][d] = (0.001f + sx) / cnt;
    }
    __syncthreads();

    if (tid < KC) {
        const int c = tid;
        float nk  = g_acc[NSUM + NS2 + c];
        float cnt = 1.0f + nk;
        float sxx = 0.0f;
        #pragma unroll
        for (int i = 0; i < 16; i++) sxx += g_acc[NSUM + c * 16 + i];
        float dot = 0.0f, a2 = 0.0f;
        #pragma unroll 8
        for (int d = 0; d < DF; d++) {
            float a = A[c][d];
            dot += a * g_acc[c * DF + (d >> 2) + 16 * (d & 3)];
            a2  += a * a;
        }
        float sq = sxx - 2.0f * dot + nk * a2;
        Si[c] = sqrtf((0.001f + sq) / cnt);
    }
    __syncthreads();

    if (tid < KC) {
        const int i = tid;
        float m = 0.0f;
        for (int j = 0; j < KC; j++) {
            if (j == i) continue;
            float ss = 0.0f;
            #pragma unroll 8
            for (int d = 0; d < DF; d++) {
                float df = A[i][d] - A[j][d];
                ss += df * df;
            }
            m = fmaxf(m, (Si[i] + Si[j]) * rsqrtf(ss));
        }
        rowmax[i] = m;
    }
    __syncthreads();

    if (tid == 0) {
        float sum = 0.0f;
        for (int c = 0; c < KC; c++) sum += rowmax[c];
        out[0] = sum / (float)KC;
    }
}

// -------------------------------------------------------------- launch ----
extern "C" void kernel_launch(void* const* d_in, const int* in_sizes, int n_in,
                              void* d_out, int out_size) {
    // binding by element-count ratio (points = 64x ids)
    const long long s0 = in_sizes[0];
    const long long s1 = (n_in > 1) ? in_sizes[1] : 0;

    const float* pts;
    const void*  cl;
    int n;
    if (s0 == 64 * s1) {
        pts = (const float*)d_in[0];
        cl  = d_in[1];
        n   = (int)s1;
    } else {
        pts = (const float*)d_in[1];
        cl  = d_in[0];
        n   = (int)s0;
    }

    int nprobe = n / 2 < 128 ? n / 2 : 128;   // in-bounds under either dtype
    dbi_init_kernel<<<(NACC + 255) / 256, 256>>>((const unsigned int*)cl, nprobe);
    dbi_accum_kernel<<<592, 256>>>(pts, cl, n);   // 4 blocks/SM, 32 warps/SM
    dbi_final_kernel<<<1, 128>>>((float*)d_out);
}

// round 13
// speedup vs baseline: 1.1574x; 1.1574x over previous
#include <cuda_runtime.h>
#include <math.h>

// DBI_44985487458968 — Davies-Bouldin index. N=2M x 64 f32, K=100.
// v3: escape the shared-atomic lane-throughput wall (measured ~2cyc/lane/SMSP,
// 66 lanes/pt = 33cyc/pt = 289us) via global red.v4.f32 into 148 L2-resident
// per-copy accumulators: 16 sum lane-ops/pt + 1 aux (sq,cnt) per point.
// Pipeline: init/probe -> accumulate (red.v4) -> copy-reduce -> finalize.

#define KC     100
#define DF     64
#define NCOPY  148
#define C_F4   1700                 // per-copy float4s: 1600 sums + 100 aux
#define COPY_F (C_F4 * 4)           // 6800 floats per copy
#define NACC   COPY_F               // reduced accumulator: 6400 sums + 100*(sq,cnt,_,_)

__device__ float4 g_scratch[NCOPY * C_F4];   // 4.03 MB, L2-resident
__device__ float  g_acc[NACC];
__device__ int    g_id64;                    // clustering int64 vs int32

__device__ __forceinline__ void red_add_v4(float4* addr, float x, float y, float z, float w) {
    asm volatile("red.global.add.v4.f32 [%0], {%1,%2,%3,%4};"
                 :: "l"(addr), "f"(x), "f"(y), "f"(z), "f"(w) : "memory");
}

// ------------------------------------------------------- init + probe ----
__global__ void dbi_init_kernel(const unsigned int* __restrict__ cl_u32, int nprobe) {
    int i = blockIdx.x * blockDim.x + threadIdx.x;
    int total = NCOPY * C_F4;
    if (i < total) g_scratch[i] = make_float4(0.f, 0.f, 0.f, 0.f);
    if (i == 0) {
        // int64 ids < 100 => every odd u32 word is zero; int32 ids make them ids.
        int any_nonzero = 0;
        for (int k = 0; k < nprobe; k++)
            any_nonzero |= (cl_u32[2 * k + 1] != 0u);
        g_id64 = !any_nonzero;
    }
}

// ---------------------------------------------------------- accumulate ----
// Half-warp per point: lanes 0-15 point j, lanes 16-31 point j+1.
// Lane l15 owns dims [4*l15, 4*l15+4) as one float4 -> one red.v4.
// sq: in-lane dot4 + 4-step xor-shuffle within width 16; lanes 0/16 emit
// one aux red.v4 = (sq, 1.0, 0, 0) covering Sxx and count together.
__global__ __launch_bounds__(256) void dbi_accum_kernel(
    const float* __restrict__ pts,
    const void*  __restrict__ cl_raw,
    int n)
{
    const int id64 = g_id64;
    const unsigned int* clu = (const unsigned int*)cl_raw;
    const float4* f4 = (const float4*)pts;

    const int lane   = threadIdx.x & 31;
    const int half   = lane >> 4;
    const int l15    = lane & 15;
    const int wGlob  = (blockIdx.x * blockDim.x + threadIdx.x) >> 5;
    const int nWarps = (gridDim.x * blockDim.x) >> 5;

    float4* base = g_scratch + (blockIdx.x % NCOPY) * C_F4;
    float4* aux  = base + 1600;

    const int nChunks = n >> 5;            // 32 points per chunk
    for (int ch = wGlob; ch < nChunks; ch += nWarps) {
        const int pbase = ch << 5;
        const int c_reg = (int)clu[id64 ? (unsigned)(2 * (pbase + lane))
                                        : (unsigned)(pbase + lane)];
        const size_t fbase = (size_t)pbase << 4;     // 16 float4 per point

        #pragma unroll 4
        for (int j = 0; j < 32; j += 2) {
            float4 v = __ldcs(&f4[fbase + (size_t)(j << 4) + lane]);
            int c = __shfl_sync(0xffffffffu, c_reg, j + half);
            float sq = v.x * v.x + v.y * v.y + v.z * v.z + v.w * v.w;
            #pragma unroll
            for (int o = 8; o; o >>= 1)
                sq += __shfl_xor_sync(0xffffffffu, sq, o, 16);
            if ((unsigned)c < KC) {
                red_add_v4(base + c * 16 + l15, v.x, v.y, v.z, v.w);
                if (l15 == 0)
                    red_add_v4(aux + c, sq, 1.0f, 0.0f, 0.0f);
            }
        }
    }

    // tail: one warp per remaining point, lanes 0-15 active
    const int tail0 = nChunks << 5;
    const int ntail = n - tail0;
    if (wGlob < ntail) {
        const int p = tail0 + wGlob;
        const int c = (int)clu[id64 ? (unsigned)(2 * p) : (unsigned)p];
        float4 v = make_float4(0.f, 0.f, 0.f, 0.f);
        if (lane < 16) v = f4[((size_t)p << 4) + l15];
        float sq = v.x * v.x + v.y * v.y + v.z * v.z + v.w * v.w;
        #pragma unroll
        for (int o = 8; o; o >>= 1)
            sq += __shfl_xor_sync(0xffffffffu, sq, o, 16);
        if ((unsigned)c < KC && lane < 16) {
            red_add_v4(base + c * 16 + l15, v.x, v.y, v.z, v.w);
            if (lane == 0)
                red_add_v4(aux + c, sq, 1.0f, 0.0f, 0.0f);
        }
    }
}

// --------------------------------------------------------- copy-reduce ----
__global__ __launch_bounds__(256) void dbi_reduce_kernel() {
    int i = blockIdx.x * blockDim.x + threadIdx.x;
    if (i >= NACC) return;
    const float* sf = (const float*)g_scratch;
    float acc = 0.0f;
    #pragma unroll 4
    for (int cpy = 0; cpy < NCOPY; cpy++)
        acc += sf[cpy * COPY_F + i];
    g_acc[i] = acc;
}

// ------------------------------------------------------------ finalize ----
__global__ __launch_bounds__(128) void dbi_final_kernel(float* __restrict__ out) {
    __shared__ float A[KC][DF];
    __shared__ float Si[KC];
    __shared__ float rowmax[KC];
    const int tid = threadIdx.x;

    // centroids: A = (0.001 + Sx) / (1 + n);  sums at g_acc[c*64+d] (natural order)
    for (int i = tid; i < KC * DF; i += blockDim.x) {
        int c = i / DF;
        float cnt = 1.0f + g_acc[6400 + c * 4 + 1];
        A[c][i - c * DF] = (0.001f + g_acc[i]) / cnt;
    }
    __syncthreads();

    // Si via  Sum||x-A||^2 = Sxx - 2 A.Sx + n ||A||^2
    if (tid < KC) {
        const int c = tid;
        float nk  = g_acc[6400 + c * 4 + 1];
        float cnt = 1.0f + nk;
        float sxx = g_acc[6400 + c * 4 + 0];
        float dot = 0.0f, a2 = 0.0f;
        #pragma unroll 8
        for (int d = 0; d < DF; d++) {
            float a = A[c][d];
            dot += a * g_acc[c * DF + d];
            a2  += a * a;
        }
        float sq = sxx - 2.0f * dot + nk * a2;
        Si[c] = sqrtf((0.001f + sq) / cnt);
    }
    __syncthreads();

    if (tid < KC) {
        const int i = tid;
        float m = 0.0f;
        for (int j = 0; j < KC; j++) {
            if (j == i) continue;
            float ss = 0.0f;
            #pragma unroll 8
            for (int d = 0; d < DF; d++) {
                float df = A[i][d] - A[j][d];
                ss += df * df;
            }
            m = fmaxf(m, (Si[i] + Si[j]) * rsqrtf(ss));
        }
        rowmax[i] = m;
    }
    __syncthreads();

    if (tid == 0) {
        float sum = 0.0f;
        for (int c = 0; c < KC; c++) sum += rowmax[c];
        out[0] = sum / (float)KC;
    }
}

// -------------------------------------------------------------- launch ----
extern "C" void kernel_launch(void* const* d_in, const int* in_sizes, int n_in,
                              void* d_out, int out_size) {
    // binding by element-count ratio (points = 64x ids)
    const long long s0 = in_sizes[0];
    const long long s1 = (n_in > 1) ? in_sizes[1] : 0;

    const float* pts;
    const void*  cl;
    int n;
    if (s0 == 64 * s1) {
        pts = (const float*)d_in[0];
        cl  = d_in[1];
        n   = (int)s1;
    } else {
        pts = (const float*)d_in[1];
        cl  = d_in[0];
        n   = (int)s0;
    }

    int nprobe = n / 2 < 128 ? n / 2 : 128;   // probe bounds safe for either dtype
    int initThreads = NCOPY * C_F4;           // one thread per float4 to zero
    dbi_init_kernel<<<(initThreads + 255) / 256, 256>>>((const unsigned int*)cl, nprobe);
    dbi_accum_kernel<<<1184, 256>>>(pts, cl, n);
    dbi_reduce_kernel<<<(NACC + 255) / 256, 256>>>();
    dbi_final_kernel<<<1, 128>>>((float*)d_out);
}